// round 3
// baseline (speedup 1.0000x reference)
#include <cuda_runtime.h>
#include <cuda_bf16.h>
#include <cstdint>

#define DHEAD 128

// Scratch (no runtime allocation allowed)
__device__ __nv_bfloat16 g_Abf[8192 * DHEAD];
__device__ __nv_bfloat16 g_Bbf[16384 * DHEAD];
__device__ float g_xsq[8192];
__device__ float g_gsq[16384];

__device__ __forceinline__ uint32_t smem_u32(const void* p) {
    uint32_t a;
    asm("{ .reg .u64 t; cvta.to.shared.u64 t, %1; cvt.u32.u64 %0, t; }" : "=r"(a) : "l"(p));
    return a;
}

// ---------------- Kernel 1: fp32 -> bf16 + row norms ----------------
__global__ void __launch_bounds__(256) convert_norm_kernel(
    const float* __restrict__ X, const float* __restrict__ G, int n_img, int n_gts)
{
    int gw = (blockIdx.x * blockDim.x + threadIdx.x) >> 5;
    int lane = threadIdx.x & 31;
    if (gw >= n_img + n_gts) return;
    const float4* src;
    uint2* dst;
    float* nrm;
    if (gw < n_img) {
        src = (const float4*)(X + (size_t)gw * DHEAD);
        dst = (uint2*)(g_Abf + (size_t)gw * DHEAD);
        nrm = g_xsq + gw;
    } else {
        int r = gw - n_img;
        src = (const float4*)(G + (size_t)r * DHEAD);
        dst = (uint2*)(g_Bbf + (size_t)r * DHEAD);
        nrm = g_gsq + r;
    }
    float4 v = src[lane];
    float s = v.x * v.x + v.y * v.y + v.z * v.z + v.w * v.w;
    #pragma unroll
    for (int o = 16; o > 0; o >>= 1) s += __shfl_xor_sync(0xFFFFFFFFu, s, o);
    __nv_bfloat162 p0 = __float22bfloat162_rn(make_float2(v.x, v.y));
    __nv_bfloat162 p1 = __float22bfloat162_rn(make_float2(v.z, v.w));
    uint2 o2;
    o2.x = *reinterpret_cast<uint32_t*>(&p0);
    o2.y = *reinterpret_cast<uint32_t*>(&p1);
    dst[lane] = o2;
    if (lane == 0) *nrm = s;
}

// ---------------- Kernel 2: HMMA (mma.sync bf16) GEMM + fused L2 epilogue ----
// Per CTA: 128x128 output tile, K=128 fully resident in SMEM.
// SMEM layout per tile: row-major [128][128] bf16 (256B rows), 16B chunks
// XOR-swizzled within the row: chunk' = chunk ^ (row & 7). This makes both
// the STS (global load) phase and the 8-row ldmatrix reads conflict-free.
//
// Warp layout: 8 warps as 2 (M) x 4 (N); each warp owns 64x32.
// Per warp: 4 m16-frags x 4 n8-frags x 8 k16-steps of mma.sync.m16n8k16.

static constexpr int SMEM_BYTES = 65536;   // 32 KB A + 32 KB B

__device__ __forceinline__ void ldmatrix_x4(uint32_t* r, uint32_t addr) {
    asm volatile("ldmatrix.sync.aligned.m8n8.x4.shared.b16 {%0,%1,%2,%3}, [%4];"
                 : "=r"(r[0]), "=r"(r[1]), "=r"(r[2]), "=r"(r[3]) : "r"(addr));
}
__device__ __forceinline__ void ldmatrix_x2(uint32_t* r, uint32_t addr) {
    asm volatile("ldmatrix.sync.aligned.m8n8.x2.shared.b16 {%0,%1}, [%2];"
                 : "=r"(r[0]), "=r"(r[1]) : "r"(addr));
}
__device__ __forceinline__ void mma_16816(float* d, const uint32_t* a, const uint32_t* b) {
    asm volatile(
        "mma.sync.aligned.m16n8k16.row.col.f32.bf16.bf16.f32 "
        "{%0,%1,%2,%3}, {%4,%5,%6,%7}, {%8,%9}, {%0,%1,%2,%3};"
        : "+f"(d[0]), "+f"(d[1]), "+f"(d[2]), "+f"(d[3])
        : "r"(a[0]), "r"(a[1]), "r"(a[2]), "r"(a[3]), "r"(b[0]), "r"(b[1]));
}

__global__ void __launch_bounds__(256, 2) l2_mma_kernel(float* __restrict__ out, int n_gts_total)
{
    extern __shared__ char smem[];
    char* sA = smem;
    char* sB = smem + 32768;
    uint32_t sAu = smem_u32(sA);
    uint32_t sBu = smem_u32(sB);

    int tid = threadIdx.x, wid = tid >> 5, lane = tid & 31;
    int ntile = blockIdx.x, mtile = blockIdx.y;

    // ---- Load A/B tiles (each 2048 16B-chunks) into swizzled SMEM ----
    const uint4* Ag = (const uint4*)(g_Abf + (size_t)mtile * 128 * DHEAD);
    const uint4* Bg = (const uint4*)(g_Bbf + (size_t)ntile * 128 * DHEAD);
    #pragma unroll
    for (int k = 0; k < 8; ++k) {
        int i = tid + k * 256;       // chunk index 0..2047
        int r = i >> 4;              // row 0..127
        int c16 = i & 15;            // 16B chunk within row
        uint32_t off = (uint32_t)r * 256u + ((uint32_t)(c16 ^ (r & 7)) << 4);
        *(uint4*)(sA + off) = Ag[i];
        *(uint4*)(sB + off) = Bg[i];
    }
    __syncthreads();

    int wr = wid >> 2;   // 0..1  (M block of 64)
    int wc = wid & 3;    // 0..3  (N block of 32)

    float d[4][4][4];
    #pragma unroll
    for (int mi = 0; mi < 4; ++mi)
        #pragma unroll
        for (int ni = 0; ni < 4; ++ni)
            #pragma unroll
            for (int j = 0; j < 4; ++j) d[mi][ni][j] = 0.0f;

    #pragma unroll
    for (int ks = 0; ks < 8; ++ks) {
        uint32_t a[4][4], b[4][2];
        #pragma unroll
        for (int mi = 0; mi < 4; ++mi) {
            int r = wr * 64 + mi * 16 + (lane & 15);
            int kc = ks * 2 + (lane >> 4);
            uint32_t addr = sAu + (uint32_t)r * 256u + ((uint32_t)(kc ^ (r & 7)) << 4);
            ldmatrix_x4(a[mi], addr);
        }
        #pragma unroll
        for (int ni = 0; ni < 4; ++ni) {
            int r = wc * 32 + ni * 8 + (lane & 7);
            int kc = ks * 2 + ((lane >> 3) & 1);
            uint32_t addr = sBu + (uint32_t)r * 256u + ((uint32_t)(kc ^ (r & 7)) << 4);
            ldmatrix_x2(b[ni], addr);
        }
        #pragma unroll
        for (int mi = 0; mi < 4; ++mi)
            #pragma unroll
            for (int ni = 0; ni < 4; ++ni)
                mma_16816(d[mi][ni], a[mi], b[ni]);
    }

    // ---- Fused epilogue: -sqrt(max(xsq + gsq - 2*xg, 0)) ----
    // Fragment layout: thread holds C[row=lane>>2 (+8)][col=(lane&3)*2 (+1)].
    int row0 = mtile * 128 + wr * 64 + (lane >> 2);
    int col0 = ntile * 128 + wc * 32 + (lane & 3) * 2;

    float xs[4][2];
    #pragma unroll
    for (int mi = 0; mi < 4; ++mi) {
        xs[mi][0] = g_xsq[row0 + mi * 16];
        xs[mi][1] = g_xsq[row0 + mi * 16 + 8];
    }
    float gs[4][2];
    #pragma unroll
    for (int ni = 0; ni < 4; ++ni) {
        float2 g2 = *(const float2*)(g_gsq + col0 + ni * 8);
        gs[ni][0] = g2.x;
        gs[ni][1] = g2.y;
    }

    #pragma unroll
    for (int mi = 0; mi < 4; ++mi) {
        #pragma unroll
        for (int h = 0; h < 2; ++h) {
            int grow = row0 + mi * 16 + h * 8;
            float* op = out + (size_t)grow * (size_t)n_gts_total;
            float xv = xs[mi][h];
            #pragma unroll
            for (int ni = 0; ni < 4; ++ni) {
                float2 o;
                float v0 = d[mi][ni][h * 2 + 0];
                float v1 = d[mi][ni][h * 2 + 1];
                float d20 = fmaxf(fmaf(-2.0f, v0, xv + gs[ni][0]), 0.0f);
                float d21 = fmaxf(fmaf(-2.0f, v1, xv + gs[ni][1]), 0.0f);
                float r0, r1;
                asm("sqrt.approx.f32 %0, %1;" : "=f"(r0) : "f"(d20));
                asm("sqrt.approx.f32 %0, %1;" : "=f"(r1) : "f"(d21));
                o.x = -r0;
                o.y = -r1;
                *(float2*)(op + col0 + ni * 8) = o;
            }
        }
    }
}

// ---------------- Launch ----------------
extern "C" void kernel_launch(void* const* d_in, const int* in_sizes, int n_in,
                              void* d_out, int out_size)
{
    const float* X = (const float*)d_in[0];   // image_features [8192,128]
    const float* G = (const float*)d_in[1];   // gts            [16384,128]
    float* out = (float*)d_out;               // [8192,16384] fp32

    int n_img = in_sizes[0] / DHEAD;
    int n_gts = in_sizes[1] / DHEAD;

    int total_warps = n_img + n_gts;
    int cblocks = (total_warps * 32 + 255) / 256;
    convert_norm_kernel<<<cblocks, 256>>>(X, G, n_img, n_gts);

    cudaFuncSetAttribute(l2_mma_kernel, cudaFuncAttributeMaxDynamicSharedMemorySize, SMEM_BYTES);
    dim3 grid(n_gts / 128, n_img / 128);
    l2_mma_kernel<<<grid, 256, SMEM_BYTES>>>(out, n_gts);
}